// round 5
// baseline (speedup 1.0000x reference)
#include <cuda_runtime.h>
#include <cuda_bf16.h>

// Sinkhorn, restructured:
//   E = exp(-C/eps) precomputed once.
//   Iteration uses bf16 copies (E_bf row-major + ET_bf transposed) -> half the
//   L2 traffic and register pressure of the R4 fp32 version. Output kernel
//   uses the fp32 E so per-element output accuracy stays fp32.
//   a = p ./ (E b + P*b_pad);  b = p ./ (E^T a + P*a_pad)   (pure GEMV loop)
//   out = 4096 * min(1, a_i * b_j * E_ij)  (block structure for the padding)
//
// Persistent iteration kernel: 128 CTAs (< SM count on B300/148 & GB300/152,
// occupancy 1 -> co-residency guaranteed), software grid barrier on per-CTA
// flag slots with release/acquire threadfences.

#define SK_N     2048
#define SK_NT    4096
#define SK_STEPS 50
#define SK_NBLK  128
#define SK_NTHR  512

__device__ float          g_E  [SK_N * SK_N];   // fp32, for k_out
__device__ __nv_bfloat16  g_Eb [SK_N * SK_N];   // bf16 row-major, iteration
__device__ __nv_bfloat16  g_ETb[SK_N * SK_N];   // bf16 transposed, iteration
__device__ float g_a[SK_N];
__device__ float g_b[SK_N];
__device__ float g_apad;
__device__ float g_bpad;
__device__ volatile unsigned g_arrive[SK_NBLK];

// ---------------------------------------------------------------------------
// Kernel 1: E = exp(-C/eps) (fp32 + bf16 + bf16-transposed), init state/flags
// ---------------------------------------------------------------------------
__global__ void k_prep(const float* __restrict__ C) {
    __shared__ float tile[32][33];
    const int bx = blockIdx.x, by = blockIdx.y;
    const int tx = threadIdx.x, ty = threadIdx.y;   // (32, 8)
    const float inv_eps = 20.0f;                    // 1/0.05

#pragma unroll
    for (int k = 0; k < 4; k++) {
        int r = by * 32 + ty + 8 * k;
        int c = bx * 32 + tx;
        float e = expf(-C[(size_t)r * SK_N + c] * inv_eps);
        g_E [(size_t)r * SK_N + c] = e;
        g_Eb[(size_t)r * SK_N + c] = __float2bfloat16(e);
        tile[ty + 8 * k][tx] = e;
    }
    __syncthreads();
#pragma unroll
    for (int k = 0; k < 4; k++) {
        int r = bx * 32 + ty + 8 * k;   // transposed row
        int c = by * 32 + tx;
        g_ETb[(size_t)r * SK_N + c] = __float2bfloat16(tile[tx][ty + 8 * k]);
    }

    if (bx == 0 && by == 0) {
        int tid = ty * 32 + tx;          // 0..255
        for (int i = tid; i < SK_N; i += 256) g_b[i] = 1.0f;   // v0 = 0 -> b = 1
        if (tid < SK_NBLK) g_arrive[tid] = 0u;
    }
}

// ---------------------------------------------------------------------------
// Kernel 2: persistent iteration kernel (128 CTAs, software grid barrier)
// ---------------------------------------------------------------------------
__device__ __forceinline__ float wred(float x) {
#pragma unroll
    for (int o = 16; o > 0; o >>= 1) x += __shfl_xor_sync(0xffffffffu, x, o);
    return x;
}

// dot( bf16 row segment (8 vals in uint4), fp32 vec segment (2 float4) )
__device__ __forceinline__ float dot8(uint4 e, float4 b0, float4 b1, float acc) {
    __nv_bfloat162 p;
    float2 f;
    p = *reinterpret_cast<__nv_bfloat162*>(&e.x); f = __bfloat1622float2(p);
    acc = fmaf(f.x, b0.x, acc); acc = fmaf(f.y, b0.y, acc);
    p = *reinterpret_cast<__nv_bfloat162*>(&e.y); f = __bfloat1622float2(p);
    acc = fmaf(f.x, b0.z, acc); acc = fmaf(f.y, b0.w, acc);
    p = *reinterpret_cast<__nv_bfloat162*>(&e.z); f = __bfloat1622float2(p);
    acc = fmaf(f.x, b1.x, acc); acc = fmaf(f.y, b1.y, acc);
    p = *reinterpret_cast<__nv_bfloat162*>(&e.w); f = __bfloat1622float2(p);
    acc = fmaf(f.x, b1.z, acc); acc = fmaf(f.y, b1.w, acc);
    return acc;
}

__global__ void __launch_bounds__(SK_NTHR, 1) k_iter() {
    __shared__ float vec[SK_N];     // 8KB staging of b (row pass) / a (col pass)
    __shared__ float wsum[16];

    const int tid  = threadIdx.x;
    const int bid  = blockIdx.x;
    const int wid  = tid >> 5;
    const int lane = tid & 31;
    const int row  = bid * 16 + wid;            // exactly one matrix row per warp
    const float P     = 2048.0f;                // padded rows/cols count
    const float PMARG = 1.0f / 4096.0f;         // p = q = 1/n

    unsigned gen = 0;
    float b_pad = 1.0f;

    for (int it = 0; it < SK_STEPS; ++it) {
        // ================= row pass: a = p / (E b + P b_pad) =================
        float4 v4 = __ldcg(((const float4*)g_b) + tid);
        ((float4*)vec)[tid] = v4;
        float part = wred(v4.x + v4.y + v4.z + v4.w);
        if (lane == 0) wsum[wid] = part;
        __syncthreads();
        float sum_b = 0.0f;
#pragma unroll
        for (int k = 0; k < 16; k++) sum_b += wsum[k];     // deterministic order
        const float a_pad = PMARG / (sum_b + P * b_pad);

        {
            const uint4*  Er = (const uint4*)(g_Eb + (size_t)row * SK_N);
            const float4* B  = (const float4*)vec;
            float acc = 0.0f;
#pragma unroll
            for (int k = 0; k < 8; k++) {
                uint4  e  = Er[lane + 32 * k];
                float4 b0 = B[(lane + 32 * k) * 2];
                float4 b1 = B[(lane + 32 * k) * 2 + 1];
                acc = dot8(e, b0, b1, acc);
            }
            acc = wred(acc);
            if (lane == 0) g_a[row] = PMARG / (acc + P * b_pad);
        }

        // ---- grid barrier (release store, spin, acquire fence) ----
        ++gen;
        __threadfence();
        __syncthreads();
        if (tid == 0) g_arrive[bid] = gen;
        if (tid < SK_NBLK) { while (g_arrive[tid] < gen) { } }
        __threadfence();
        __syncthreads();

        // ================= col pass: b = p / (E^T a + P a_pad) ===============
        float4 a4 = __ldcg(((const float4*)g_a) + tid);
        ((float4*)vec)[tid] = a4;
        float parta = wred(a4.x + a4.y + a4.z + a4.w);
        if (lane == 0) wsum[wid] = parta;
        __syncthreads();
        float sum_a = 0.0f;
#pragma unroll
        for (int k = 0; k < 16; k++) sum_a += wsum[k];
        b_pad = PMARG / (sum_a + P * a_pad);

        {
            const uint4*  Er = (const uint4*)(g_ETb + (size_t)row * SK_N);
            const float4* A  = (const float4*)vec;
            float acc = 0.0f;
#pragma unroll
            for (int k = 0; k < 8; k++) {
                uint4  e  = Er[lane + 32 * k];
                float4 a0 = A[(lane + 32 * k) * 2];
                float4 a1 = A[(lane + 32 * k) * 2 + 1];
                acc = dot8(e, a0, a1, acc);
            }
            acc = wred(acc);
            if (lane == 0) g_b[row] = PMARG / (acc + P * a_pad);
        }

        if (it == SK_STEPS - 1 && bid == 0 && tid == 0) {
            g_apad = a_pad;
            g_bpad = b_pad;
        }

        // ---- grid barrier ----
        ++gen;
        __threadfence();
        __syncthreads();
        if (tid == 0) g_arrive[bid] = gen;
        if (tid < SK_NBLK) { while (g_arrive[tid] < gen) { } }
        __threadfence();
        __syncthreads();
    }
}

// ---------------------------------------------------------------------------
// Kernel 3: out[i][j] = 4096 * min(1, a_i * b_j * E_ij), with padded blocks
// (uses fp32 E for full output precision)
// ---------------------------------------------------------------------------
__global__ void k_out(float* __restrict__ out) {
    const int i = blockIdx.x;                 // 0..4095 (one output row)
    const float S  = 4096.0f;
    const float ap = g_apad;
    const float bp = g_bpad;
    float4* orow = (float4*)(out + (size_t)i * SK_NT);
    const float4* B4 = (const float4*)g_b;

    if (i < SK_N) {
        const float ai = g_a[i];
        const float4* Er = (const float4*)(g_E + (size_t)i * SK_N);
        for (int t = threadIdx.x; t < 512; t += blockDim.x) {
            float4 e = Er[t], b = B4[t], r;
            r.x = S * fminf(1.0f, ai * b.x * e.x);
            r.y = S * fminf(1.0f, ai * b.y * e.y);
            r.z = S * fminf(1.0f, ai * b.z * e.z);
            r.w = S * fminf(1.0f, ai * b.w * e.w);
            orow[t] = r;
        }
        float c = S * fminf(1.0f, ai * bp);
        float4 c4 = make_float4(c, c, c, c);
        for (int t = threadIdx.x; t < 512; t += blockDim.x) orow[512 + t] = c4;
    } else {
        for (int t = threadIdx.x; t < 512; t += blockDim.x) {
            float4 b = B4[t], r;
            r.x = S * fminf(1.0f, ap * b.x);
            r.y = S * fminf(1.0f, ap * b.y);
            r.z = S * fminf(1.0f, ap * b.z);
            r.w = S * fminf(1.0f, ap * b.w);
            orow[t] = r;
        }
        float c = S * fminf(1.0f, ap * bp);
        float4 c4 = make_float4(c, c, c, c);
        for (int t = threadIdx.x; t < 512; t += blockDim.x) orow[512 + t] = c4;
    }
}

// ---------------------------------------------------------------------------
extern "C" void kernel_launch(void* const* d_in, const int* in_sizes, int n_in,
                              void* d_out, int out_size) {
    const float* C = (const float*)d_in[0];
    float* out = (float*)d_out;

    dim3 tg(32, 8);
    dim3 bg(SK_N / 32, SK_N / 32);
    k_prep<<<bg, tg>>>(C);
    k_iter<<<SK_NBLK, SK_NTHR>>>();
    k_out<<<SK_NT, 256>>>(out);
}

// round 6
// speedup vs baseline: 2.5805x; 2.5805x over previous
#include <cuda_runtime.h>
#include <cuda_bf16.h>

// Sinkhorn, restructured:
//   E = exp(-C/eps) precomputed once (fp32 for output; bf16 row-major +
//   bf16 transposed for the iteration GEMVs).
//   a = p ./ (E b + P*b_pad);  b = p ./ (E^T a + P*a_pad)   (pure GEMV loop)
//   out = 4096 * min(1, a_i * b_j * E_ij)  (block structure for the padding)
//
// Persistent iteration kernel, 128 CTAs. Grid barrier = single global arrival
// counter: tid0 red.release.gpu.add + tid0-only ld.acquire.gpu poll. This
// avoids the R5 failure mode (128 pollers/CTA flooding the per-SM L1tex FIFO
// + per-thread gpu-scope membars), which made the loop traffic-independent.

#define SK_N     2048
#define SK_NT    4096
#define SK_STEPS 50
#define SK_NBLK  128
#define SK_NTHR  512

__device__ float          g_E  [SK_N * SK_N];   // fp32, for k_out
__device__ __nv_bfloat16  g_Eb [SK_N * SK_N];   // bf16 row-major, iteration
__device__ __nv_bfloat16  g_ETb[SK_N * SK_N];   // bf16 transposed, iteration
__device__ float g_a[SK_N];
__device__ float g_b[SK_N];
__device__ float g_apad;
__device__ float g_bpad;
__device__ unsigned g_count;                    // barrier arrival counter

// ---------------------------------------------------------------------------
// Kernel 1: E = exp(-C/eps) (fp32 + bf16 + bf16-transposed), init state/flags
// ---------------------------------------------------------------------------
__global__ void k_prep(const float* __restrict__ C) {
    __shared__ float tile[32][33];
    const int bx = blockIdx.x, by = blockIdx.y;
    const int tx = threadIdx.x, ty = threadIdx.y;   // (32, 8)
    const float inv_eps = 20.0f;                    // 1/0.05

#pragma unroll
    for (int k = 0; k < 4; k++) {
        int r = by * 32 + ty + 8 * k;
        int c = bx * 32 + tx;
        float e = expf(-C[(size_t)r * SK_N + c] * inv_eps);
        g_E [(size_t)r * SK_N + c] = e;
        g_Eb[(size_t)r * SK_N + c] = __float2bfloat16(e);
        tile[ty + 8 * k][tx] = e;
    }
    __syncthreads();
#pragma unroll
    for (int k = 0; k < 4; k++) {
        int r = bx * 32 + ty + 8 * k;   // transposed row
        int c = by * 32 + tx;
        g_ETb[(size_t)r * SK_N + c] = __float2bfloat16(tile[tx][ty + 8 * k]);
    }

    if (bx == 0 && by == 0) {
        int tid = ty * 32 + tx;          // 0..255
        for (int i = tid; i < SK_N; i += 256) g_b[i] = 1.0f;   // v0 = 0 -> b = 1
        if (tid == 0) g_count = 0u;      // reset every launch (graph replay safe)
    }
}

// ---------------------------------------------------------------------------
// Kernel 2: persistent iteration kernel (128 CTAs, counter grid barrier)
// ---------------------------------------------------------------------------
__device__ __forceinline__ float wred(float x) {
#pragma unroll
    for (int o = 16; o > 0; o >>= 1) x += __shfl_xor_sync(0xffffffffu, x, o);
    return x;
}

// Grid barrier: prior CTA stores -> syncthreads (HB edge to tid0) ->
// release-arrive -> acquire-poll (tid0 only) -> syncthreads.
__device__ __forceinline__ void grid_barrier(unsigned target) {
    __syncthreads();
    if (threadIdx.x == 0) {
        asm volatile("red.release.gpu.global.add.u32 [%0], 1;"
                     :: "l"(&g_count) : "memory");
        unsigned v;
        do {
            asm volatile("ld.acquire.gpu.global.u32 %0, [%1];"
                         : "=r"(v) : "l"(&g_count) : "memory");
        } while (v < target);
    }
    __syncthreads();
}

// dot( bf16 row segment (8 vals in uint4), fp32 vec segment (2 float4) )
__device__ __forceinline__ float dot8(uint4 e, float4 b0, float4 b1, float acc) {
    __nv_bfloat162 p;
    float2 f;
    p = *reinterpret_cast<__nv_bfloat162*>(&e.x); f = __bfloat1622float2(p);
    acc = fmaf(f.x, b0.x, acc); acc = fmaf(f.y, b0.y, acc);
    p = *reinterpret_cast<__nv_bfloat162*>(&e.y); f = __bfloat1622float2(p);
    acc = fmaf(f.x, b0.z, acc); acc = fmaf(f.y, b0.w, acc);
    p = *reinterpret_cast<__nv_bfloat162*>(&e.z); f = __bfloat1622float2(p);
    acc = fmaf(f.x, b1.x, acc); acc = fmaf(f.y, b1.y, acc);
    p = *reinterpret_cast<__nv_bfloat162*>(&e.w); f = __bfloat1622float2(p);
    acc = fmaf(f.x, b1.z, acc); acc = fmaf(f.y, b1.w, acc);
    return acc;
}

__global__ void __launch_bounds__(SK_NTHR, 1) k_iter() {
    __shared__ float vec[SK_N];     // 8KB staging of b (row pass) / a (col pass)
    __shared__ float wsum[16];

    const int tid  = threadIdx.x;
    const int bid  = blockIdx.x;
    const int wid  = tid >> 5;
    const int lane = tid & 31;
    const int row  = bid * 16 + wid;            // exactly one matrix row per warp
    const float P     = 2048.0f;                // padded rows/cols count
    const float PMARG = 1.0f / 4096.0f;         // p = q = 1/n

    unsigned gen = 0;
    float b_pad = 1.0f;

    for (int it = 0; it < SK_STEPS; ++it) {
        // ================= row pass: a = p / (E b + P b_pad) =================
        float4 v4 = __ldcg(((const float4*)g_b) + tid);
        ((float4*)vec)[tid] = v4;
        float part = wred(v4.x + v4.y + v4.z + v4.w);
        if (lane == 0) wsum[wid] = part;
        __syncthreads();
        float sum_b = 0.0f;
#pragma unroll
        for (int k = 0; k < 16; k++) sum_b += wsum[k];     // deterministic order
        const float a_pad = PMARG / (sum_b + P * b_pad);

        {
            const uint4*  Er = (const uint4*)(g_Eb + (size_t)row * SK_N);
            const float4* B  = (const float4*)vec;
            float acc0 = 0.0f, acc1 = 0.0f, acc2 = 0.0f, acc3 = 0.0f;
#pragma unroll
            for (int k = 0; k < 8; k += 4) {
                uint4 e0 = Er[lane + 32 * (k + 0)];
                uint4 e1 = Er[lane + 32 * (k + 1)];
                uint4 e2 = Er[lane + 32 * (k + 2)];
                uint4 e3 = Er[lane + 32 * (k + 3)];
                acc0 = dot8(e0, B[(lane + 32*(k+0))*2], B[(lane + 32*(k+0))*2+1], acc0);
                acc1 = dot8(e1, B[(lane + 32*(k+1))*2], B[(lane + 32*(k+1))*2+1], acc1);
                acc2 = dot8(e2, B[(lane + 32*(k+2))*2], B[(lane + 32*(k+2))*2+1], acc2);
                acc3 = dot8(e3, B[(lane + 32*(k+3))*2], B[(lane + 32*(k+3))*2+1], acc3);
            }
            float acc = wred((acc0 + acc1) + (acc2 + acc3));
            if (lane == 0) g_a[row] = PMARG / (acc + P * b_pad);
        }

        grid_barrier(++gen * SK_NBLK);

        // ================= col pass: b = p / (E^T a + P a_pad) ===============
        float4 a4 = __ldcg(((const float4*)g_a) + tid);
        ((float4*)vec)[tid] = a4;
        float parta = wred(a4.x + a4.y + a4.z + a4.w);
        if (lane == 0) wsum[wid] = parta;
        __syncthreads();
        float sum_a = 0.0f;
#pragma unroll
        for (int k = 0; k < 16; k++) sum_a += wsum[k];
        b_pad = PMARG / (sum_a + P * a_pad);

        {
            const uint4*  Er = (const uint4*)(g_ETb + (size_t)row * SK_N);
            const float4* A  = (const float4*)vec;
            float acc0 = 0.0f, acc1 = 0.0f, acc2 = 0.0f, acc3 = 0.0f;
#pragma unroll
            for (int k = 0; k < 8; k += 4) {
                uint4 e0 = Er[lane + 32 * (k + 0)];
                uint4 e1 = Er[lane + 32 * (k + 1)];
                uint4 e2 = Er[lane + 32 * (k + 2)];
                uint4 e3 = Er[lane + 32 * (k + 3)];
                acc0 = dot8(e0, A[(lane + 32*(k+0))*2], A[(lane + 32*(k+0))*2+1], acc0);
                acc1 = dot8(e1, A[(lane + 32*(k+1))*2], A[(lane + 32*(k+1))*2+1], acc1);
                acc2 = dot8(e2, A[(lane + 32*(k+2))*2], A[(lane + 32*(k+2))*2+1], acc2);
                acc3 = dot8(e3, A[(lane + 32*(k+3))*2], A[(lane + 32*(k+3))*2+1], acc3);
            }
            float acc = wred((acc0 + acc1) + (acc2 + acc3));
            if (lane == 0) g_b[row] = PMARG / (acc + P * a_pad);
        }

        if (it == SK_STEPS - 1 && bid == 0 && tid == 0) {
            g_apad = a_pad;
            g_bpad = b_pad;
        }

        grid_barrier(++gen * SK_NBLK);
    }
}

// ---------------------------------------------------------------------------
// Kernel 3: out[i][j] = 4096 * min(1, a_i * b_j * E_ij), with padded blocks
// (uses fp32 E for full output precision)
// ---------------------------------------------------------------------------
__global__ void k_out(float* __restrict__ out) {
    const int i = blockIdx.x;                 // 0..4095 (one output row)
    const float S  = 4096.0f;
    const float ap = g_apad;
    const float bp = g_bpad;
    float4* orow = (float4*)(out + (size_t)i * SK_NT);
    const float4* B4 = (const float4*)g_b;

    if (i < SK_N) {
        const float ai = g_a[i];
        const float4* Er = (const float4*)(g_E + (size_t)i * SK_N);
        for (int t = threadIdx.x; t < 512; t += blockDim.x) {
            float4 e = Er[t], b = B4[t], r;
            r.x = S * fminf(1.0f, ai * b.x * e.x);
            r.y = S * fminf(1.0f, ai * b.y * e.y);
            r.z = S * fminf(1.0f, ai * b.z * e.z);
            r.w = S * fminf(1.0f, ai * b.w * e.w);
            orow[t] = r;
        }
        float c = S * fminf(1.0f, ai * bp);
        float4 c4 = make_float4(c, c, c, c);
        for (int t = threadIdx.x; t < 512; t += blockDim.x) orow[512 + t] = c4;
    } else {
        for (int t = threadIdx.x; t < 512; t += blockDim.x) {
            float4 b = B4[t], r;
            r.x = S * fminf(1.0f, ap * b.x);
            r.y = S * fminf(1.0f, ap * b.y);
            r.z = S * fminf(1.0f, ap * b.z);
            r.w = S * fminf(1.0f, ap * b.w);
            orow[t] = r;
        }
        float c = S * fminf(1.0f, ap * bp);
        float4 c4 = make_float4(c, c, c, c);
        for (int t = threadIdx.x; t < 512; t += blockDim.x) orow[512 + t] = c4;
    }
}

// ---------------------------------------------------------------------------
extern "C" void kernel_launch(void* const* d_in, const int* in_sizes, int n_in,
                              void* d_out, int out_size) {
    const float* C = (const float*)d_in[0];
    float* out = (float*)d_out;

    dim3 tg(32, 8);
    dim3 bg(SK_N / 32, SK_N / 32);
    k_prep<<<bg, tg>>>(C);
    k_iter<<<SK_NBLK, SK_NTHR>>>();
    k_out<<<SK_NT, 256>>>(out);
}

// round 7
// speedup vs baseline: 2.8337x; 1.0981x over previous
#include <cuda_runtime.h>
#include <cuda_bf16.h>

// Sinkhorn, restructured:
//   E = exp(-C/eps) in bf16 (row-major + transposed) for the iteration GEMVs;
//   k_out recomputes fp32 E from C directly (no fp32 E array).
//   a = p ./ (E b + P*b_pad);  b = p ./ (E^T a + P*a_pad)   (pure GEMV loop)
//   out = 4096 * min(1, a_i * b_j * E_ij)  (block structure for the padding)
//
// Persistent iteration kernel, 128 CTAs, single-counter grid barrier
// (tid0 red.release.gpu + tid0 acquire poll). NEW in this round: each warp
// prefetches its NEXT-phase E/ET row into registers BEFORE entering the
// barrier, so the static-matrix load latency overlaps the barrier wait and
// is off the post-barrier critical path (registers survive L1 invalidations
// from the gpu-scope acquire/release traffic).

#define SK_N     2048
#define SK_NT    4096
#define SK_STEPS 50
#define SK_NBLK  128
#define SK_NTHR  512

__device__ __nv_bfloat16  g_Eb [SK_N * SK_N];   // bf16 row-major, iteration
__device__ __nv_bfloat16  g_ETb[SK_N * SK_N];   // bf16 transposed, iteration
__device__ float g_a[SK_N];
__device__ float g_b[SK_N];
__device__ float g_apad;
__device__ float g_bpad;
__device__ unsigned g_count;                    // barrier arrival counter

// ---------------------------------------------------------------------------
// Kernel 1: Eb = bf16(exp(-C/eps)) + transposed copy, init state/counter
// ---------------------------------------------------------------------------
__global__ void k_prep(const float* __restrict__ C) {
    __shared__ float tile[32][33];
    const int bx = blockIdx.x, by = blockIdx.y;
    const int tx = threadIdx.x, ty = threadIdx.y;   // (32, 8)
    const float inv_eps = 20.0f;                    // 1/0.05

#pragma unroll
    for (int k = 0; k < 4; k++) {
        int r = by * 32 + ty + 8 * k;
        int c = bx * 32 + tx;
        float e = expf(-C[(size_t)r * SK_N + c] * inv_eps);
        g_Eb[(size_t)r * SK_N + c] = __float2bfloat16(e);
        tile[ty + 8 * k][tx] = e;
    }
    __syncthreads();
#pragma unroll
    for (int k = 0; k < 4; k++) {
        int r = bx * 32 + ty + 8 * k;   // transposed row
        int c = by * 32 + tx;
        g_ETb[(size_t)r * SK_N + c] = __float2bfloat16(tile[tx][ty + 8 * k]);
    }

    if (bx == 0 && by == 0) {
        int tid = ty * 32 + tx;          // 0..255
        for (int i = tid; i < SK_N; i += 256) g_b[i] = 1.0f;   // v0 = 0 -> b = 1
        if (tid == 0) g_count = 0u;      // reset every launch (graph replay safe)
    }
}

// ---------------------------------------------------------------------------
// Kernel 2: persistent iteration kernel (128 CTAs, counter grid barrier)
// ---------------------------------------------------------------------------
__device__ __forceinline__ float wred(float x) {
#pragma unroll
    for (int o = 16; o > 0; o >>= 1) x += __shfl_xor_sync(0xffffffffu, x, o);
    return x;
}

// Grid barrier: prior CTA stores -> syncthreads (HB edge to tid0) ->
// release-arrive -> acquire-poll (tid0 only) -> syncthreads.
__device__ __forceinline__ void grid_barrier(unsigned target) {
    __syncthreads();
    if (threadIdx.x == 0) {
        asm volatile("red.release.gpu.global.add.u32 [%0], 1;"
                     :: "l"(&g_count) : "memory");
        unsigned v;
        do {
            asm volatile("ld.acquire.gpu.global.u32 %0, [%1];"
                         : "=r"(v) : "l"(&g_count) : "memory");
        } while (v < target);
    }
    __syncthreads();
}

// dot( bf16 row segment (8 vals in uint4), fp32 vec segment (2 float4) )
__device__ __forceinline__ float dot8(uint4 e, float4 b0, float4 b1, float acc) {
    __nv_bfloat162 p;
    float2 f;
    p = *reinterpret_cast<__nv_bfloat162*>(&e.x); f = __bfloat1622float2(p);
    acc = fmaf(f.x, b0.x, acc); acc = fmaf(f.y, b0.y, acc);
    p = *reinterpret_cast<__nv_bfloat162*>(&e.y); f = __bfloat1622float2(p);
    acc = fmaf(f.x, b0.z, acc); acc = fmaf(f.y, b0.w, acc);
    p = *reinterpret_cast<__nv_bfloat162*>(&e.z); f = __bfloat1622float2(p);
    acc = fmaf(f.x, b1.x, acc); acc = fmaf(f.y, b1.y, acc);
    p = *reinterpret_cast<__nv_bfloat162*>(&e.w); f = __bfloat1622float2(p);
    acc = fmaf(f.x, b1.z, acc); acc = fmaf(f.y, b1.w, acc);
    return acc;
}

__global__ void __launch_bounds__(SK_NTHR, 1) k_iter() {
    __shared__ float vec[SK_N];     // 8KB staging of b (row pass) / a (col pass)
    __shared__ float wsum[16];

    const int tid  = threadIdx.x;
    const int bid  = blockIdx.x;
    const int wid  = tid >> 5;
    const int lane = tid & 31;
    const int row  = bid * 16 + wid;            // exactly one matrix row per warp
    const float P     = 2048.0f;                // padded rows/cols count
    const float PMARG = 1.0f / 4096.0f;         // p = q = 1/n

    const uint4* Erow  = (const uint4*)(g_Eb  + (size_t)row * SK_N);
    const uint4* ETrow = (const uint4*)(g_ETb + (size_t)row * SK_N);

    unsigned gen = 0;
    float b_pad = 1.0f;

    // Prefetch E row for the first row pass.
    uint4 eb[8];
#pragma unroll
    for (int k = 0; k < 8; k++) eb[k] = Erow[lane + 32 * k];

    for (int it = 0; it < SK_STEPS; ++it) {
        // ================= row pass: a = p / (E b + P b_pad) =================
        float4 v4 = __ldcg(((const float4*)g_b) + tid);
        ((float4*)vec)[tid] = v4;
        float part = wred(v4.x + v4.y + v4.z + v4.w);
        if (lane == 0) wsum[wid] = part;
        __syncthreads();
        float sum_b = 0.0f;
#pragma unroll
        for (int k = 0; k < 16; k++) sum_b += wsum[k];     // deterministic order
        const float a_pad = PMARG / (sum_b + P * b_pad);

        {
            const float4* B = (const float4*)vec;
            float acc0 = 0.0f, acc1 = 0.0f, acc2 = 0.0f, acc3 = 0.0f;
#pragma unroll
            for (int k = 0; k < 8; k += 4) {
                acc0 = dot8(eb[k+0], B[(lane + 32*(k+0))*2], B[(lane + 32*(k+0))*2+1], acc0);
                acc1 = dot8(eb[k+1], B[(lane + 32*(k+1))*2], B[(lane + 32*(k+1))*2+1], acc1);
                acc2 = dot8(eb[k+2], B[(lane + 32*(k+2))*2], B[(lane + 32*(k+2))*2+1], acc2);
                acc3 = dot8(eb[k+3], B[(lane + 32*(k+3))*2], B[(lane + 32*(k+3))*2+1], acc3);
            }
            float acc = wred((acc0 + acc1) + (acc2 + acc3));
            if (lane == 0) g_a[row] = PMARG / (acc + P * b_pad);
        }

        // Prefetch ET row for the col pass; loads overlap the barrier wait.
#pragma unroll
        for (int k = 0; k < 8; k++) eb[k] = ETrow[lane + 32 * k];

        grid_barrier(++gen * SK_NBLK);

        // ================= col pass: b = p / (E^T a + P a_pad) ===============
        float4 a4 = __ldcg(((const float4*)g_a) + tid);
        ((float4*)vec)[tid] = a4;
        float parta = wred(a4.x + a4.y + a4.z + a4.w);
        if (lane == 0) wsum[wid] = parta;
        __syncthreads();
        float sum_a = 0.0f;
#pragma unroll
        for (int k = 0; k < 16; k++) sum_a += wsum[k];
        b_pad = PMARG / (sum_a + P * a_pad);

        {
            const float4* A = (const float4*)vec;
            float acc0 = 0.0f, acc1 = 0.0f, acc2 = 0.0f, acc3 = 0.0f;
#pragma unroll
            for (int k = 0; k < 8; k += 4) {
                acc0 = dot8(eb[k+0], A[(lane + 32*(k+0))*2], A[(lane + 32*(k+0))*2+1], acc0);
                acc1 = dot8(eb[k+1], A[(lane + 32*(k+1))*2], A[(lane + 32*(k+1))*2+1], acc1);
                acc2 = dot8(eb[k+2], A[(lane + 32*(k+2))*2], A[(lane + 32*(k+2))*2+1], acc2);
                acc3 = dot8(eb[k+3], A[(lane + 32*(k+3))*2], A[(lane + 32*(k+3))*2+1], acc3);
            }
            float acc = wred((acc0 + acc1) + (acc2 + acc3));
            if (lane == 0) g_b[row] = PMARG / (acc + P * a_pad);
        }

        if (it == SK_STEPS - 1 && bid == 0 && tid == 0) {
            g_apad = a_pad;
            g_bpad = b_pad;
        }

        // Prefetch E row for the next row pass; overlaps the barrier wait.
#pragma unroll
        for (int k = 0; k < 8; k++) eb[k] = Erow[lane + 32 * k];

        grid_barrier(++gen * SK_NBLK);
    }
}

// ---------------------------------------------------------------------------
// Kernel 3: out[i][j] = 4096 * min(1, a_i * b_j * exp(-C_ij/eps)), padded blk
// (recomputes fp32 E from C -> full fp32 output precision, no fp32 E array)
// ---------------------------------------------------------------------------
__global__ void k_out(float* __restrict__ out, const float* __restrict__ C) {
    const int i = blockIdx.x;                 // 0..4095 (one output row)
    const float S  = 4096.0f;
    const float inv_eps = 20.0f;
    const float ap = g_apad;
    const float bp = g_bpad;
    float4* orow = (float4*)(out + (size_t)i * SK_NT);
    const float4* B4 = (const float4*)g_b;

    if (i < SK_N) {
        const float ai = g_a[i];
        const float4* Cr = (const float4*)(C + (size_t)i * SK_N);
        for (int t = threadIdx.x; t < 512; t += blockDim.x) {
            float4 c = Cr[t], b = B4[t], r;
            r.x = S * fminf(1.0f, ai * b.x * __expf(-c.x * inv_eps));
            r.y = S * fminf(1.0f, ai * b.y * __expf(-c.y * inv_eps));
            r.z = S * fminf(1.0f, ai * b.z * __expf(-c.z * inv_eps));
            r.w = S * fminf(1.0f, ai * b.w * __expf(-c.w * inv_eps));
            orow[t] = r;
        }
        float cpad = S * fminf(1.0f, ai * bp);
        float4 c4 = make_float4(cpad, cpad, cpad, cpad);
        for (int t = threadIdx.x; t < 512; t += blockDim.x) orow[512 + t] = c4;
    } else {
        for (int t = threadIdx.x; t < 512; t += blockDim.x) {
            float4 b = B4[t], r;
            r.x = S * fminf(1.0f, ap * b.x);
            r.y = S * fminf(1.0f, ap * b.y);
            r.z = S * fminf(1.0f, ap * b.z);
            r.w = S * fminf(1.0f, ap * b.w);
            orow[t] = r;
        }
        float cpad = S * fminf(1.0f, ap * bp);
        float4 c4 = make_float4(cpad, cpad, cpad, cpad);
        for (int t = threadIdx.x; t < 512; t += blockDim.x) orow[512 + t] = c4;
    }
}

// ---------------------------------------------------------------------------
extern "C" void kernel_launch(void* const* d_in, const int* in_sizes, int n_in,
                              void* d_out, int out_size) {
    const float* C = (const float*)d_in[0];
    float* out = (float*)d_out;

    dim3 tg(32, 8);
    dim3 bg(SK_N / 32, SK_N / 32);
    k_prep<<<bg, tg>>>(C);
    k_iter<<<SK_NBLK, SK_NTHR>>>();
    k_out<<<SK_NT, 256>>>(out, C);
}